// round 5
// baseline (speedup 1.0000x reference)
#include <cuda_runtime.h>

// Idx2PixelLayer bilinear gather — row-binned two-phase version.
//  P0: zero bin counters
//  P1: compute (c, d, i) per point, append 16B record to row-bin (atomic)
//  P2: per-bin cooperative gather (4 lanes/point) with strong L2 / DRAM-row
//      locality; scattered 32B stores to out (sector-exact).

#define HW    2048
#define CCH   8
#define NBINS 2048          // one bin per image row i0
#define CAP   1536          // mean ~490 pts/bin, Poisson max ~650 — ample
#define BPB   8             // bins per block in P2

__device__ int    g_cnt[NBINS];
__device__ float4 g_rec[(size_t)NBINS * CAP];   // {d0, d1, packed(i0,i1), pid}

__device__ __forceinline__ float2 ldg_cs2(const float* p) {
    float2 v;
    asm volatile("ld.global.cs.v2.f32 {%0,%1}, [%2];"
                 : "=f"(v.x), "=f"(v.y) : "l"(p));
    return v;
}
__device__ __forceinline__ void stg_cs4(float* p, float4 v) {
    asm volatile("st.global.cs.v4.f32 [%0], {%1,%2,%3,%4};"
                 :: "l"(p), "f"(v.x), "f"(v.y), "f"(v.z), "f"(v.w) : "memory");
}

__global__ void zero_kernel() {
    int t = blockIdx.x * blockDim.x + threadIdx.x;
    if (t < NBINS) g_cnt[t] = 0;
}

// ---------------- P1: scatter points into row bins ----------------
__global__ __launch_bounds__(256) void scatter_kernel(
    const float* __restrict__ coords,
    const float* __restrict__ vis,
    float* __restrict__ out,
    int n)
{
    int t = blockIdx.x * blockDim.x + threadIdx.x;
    if (t >= n) return;

    float2 xy = ldg_cs2(coords + (size_t)t * 2);
    const float M = (float)(HW - 4);   // 2044

    float c0 = fmodf(xy.x - 1.0f, M); if (c0 < 0.0f) c0 += M; c0 += 1.0f;
    float c1 = fmodf(xy.y - 1.0f, M); if (c1 < 0.0f) c1 += M; c1 += 1.0f;

    float f0 = floorf(c0), f1 = floorf(c1);
    float d0 = c0 - f0,   d1 = c1 - f1;
    int   i0 = (int)f0,   i1 = (int)f1;

    int bin  = i0 & (NBINS - 1);
    int slot = atomicAdd(&g_cnt[bin], 1);
    if (slot < CAP) {
        float4 r;
        r.x = d0; r.y = d1;
        r.z = __int_as_float((i0 << 11) | i1);
        r.w = __int_as_float(t);
        g_rec[(size_t)bin * CAP + slot] = r;
    } else {
        // overflow fallback (never hit for uniform coords): compute directly
        const float* p0 = vis + ((size_t)i0 * HW + i1) * CCH;
        const float* p1 = p0 + (size_t)HW * CCH;
        #pragma unroll
        for (int ch = 0; ch < CCH; ch++) {
            float tl = p0[ch],        bl = p0[CCH + ch];
            float tr = p1[ch],        br = p1[CCH + ch];
            float mb = br + d0 * (bl - br);
            float mt = tr + d0 * (tl - tr);
            out[(size_t)t * CCH + ch] = mb + d1 * (mt - mb);
        }
    }
}

// ---------------- P2: process bins with 4-lane cooperative gather ----------------
__global__ __launch_bounds__(256) void process_kernel(
    const float* __restrict__ vis,
    float* __restrict__ out)
{
    int lane  = threadIdx.x & 31;
    int w     = threadIdx.x >> 5;     // warp 0..7
    int group = lane >> 2;            // 0..7
    int j     = lane & 3;             // 0..3

    for (int b = 0; b < BPB; b++) {
        int bin   = blockIdx.x * BPB + b;
        int count = min(g_cnt[bin], CAP);
        const float4* recs = g_rec + (size_t)bin * CAP;

        for (int base = 0; base < count; base += 64) {
            int  s     = base + w * 8 + group;
            bool valid = s < count;

            float4 r = make_float4(0.f, 0.f, 0.f, 0.f);
            if (valid) r = recs[s];
            float d0 = r.x, d1 = r.y;
            int packed = __float_as_int(r.z);
            int pid    = __float_as_int(r.w);
            int i0 = packed >> 11;
            int i1 = packed & 2047;

            const float* pA = vis + ((size_t)i0 * HW + i1) * CCH + j * 4;
            const float* pB = pA + (size_t)HW * CCH;

            float4 A = make_float4(0.f, 0.f, 0.f, 0.f);
            float4 B = A;
            if (valid) {
                A = __ldg(reinterpret_cast<const float4*>(pA));  // tl/bl half
                B = __ldg(reinterpret_cast<const float4*>(pB));  // tr/br half
            }

            // lanes 0,1 -> mt = tr + d0*(tl-tr); lanes 2,3 -> mb = br + d0*(bl-br)
            float4 v;
            v.x = B.x + d0 * (A.x - B.x);
            v.y = B.y + d0 * (A.y - B.y);
            v.z = B.z + d0 * (A.z - B.z);
            v.w = B.w + d0 * (A.w - B.w);

            float4 o;
            o.x = __shfl_xor_sync(0xffffffffu, v.x, 2);
            o.y = __shfl_xor_sync(0xffffffffu, v.y, 2);
            o.z = __shfl_xor_sync(0xffffffffu, v.z, 2);
            o.w = __shfl_xor_sync(0xffffffffu, v.w, 2);

            float4 mt, mb;
            if (j < 2) { mt = v; mb = o; } else { mt = o; mb = v; }

            float4 res;
            res.x = mb.x + d1 * (mt.x - mb.x);
            res.y = mb.y + d1 * (mt.y - mb.y);
            res.z = mb.z + d1 * (mt.z - mb.z);
            res.w = mb.w + d1 * (mt.w - mb.w);

            // off = c > 2048 never true (c in [1, 2045]): no zeroing.
            if (valid && j < 2)
                stg_cs4(out + (size_t)pid * CCH + j * 4, res);
        }
    }
}

extern "C" void kernel_launch(void* const* d_in, const int* in_sizes, int n_in,
                              void* d_out, int out_size)
{
    const float* coords = (const float*)d_in[0];
    const float* vis    = (const float*)d_in[1];
    float* out          = (float*)d_out;

    int n = in_sizes[0] / 2;   // number of points

    zero_kernel<<<(NBINS + 255) / 256, 256>>>();
    scatter_kernel<<<(n + 255) / 256, 256>>>(coords, vis, out, n);
    process_kernel<<<NBINS / BPB, 256>>>(vis, out);
}

// round 6
// speedup vs baseline: 3.6395x; 3.6395x over previous
#include <cuda_runtime.h>

// Idx2PixelLayer bilinear gather — cooperative 4-lanes-per-point,
// 4 points per lane-group (8 gather loads in flight per thread).
//   visible : ld.global.nc.L2::cache_hint (evict_last)
//   coords  : ld.global.cs ; out : st.global.cs

#define HW 2048
#define CCH 8

__device__ __forceinline__ unsigned long long mk_policy_el() {
    unsigned long long p;
    asm("createpolicy.fractional.L2::evict_last.b64 %0, 1.0;" : "=l"(p));
    return p;
}

__device__ __forceinline__ float4 ldg_vis(const float* p, unsigned long long pol) {
    float4 v;
    asm volatile("ld.global.nc.L2::cache_hint.v4.f32 {%0,%1,%2,%3}, [%4], %5;"
                 : "=f"(v.x), "=f"(v.y), "=f"(v.z), "=f"(v.w)
                 : "l"(p), "l"(pol));
    return v;
}

__device__ __forceinline__ float4 ldg_stream4(const float* p) {
    float4 v;
    asm volatile("ld.global.cs.v4.f32 {%0,%1,%2,%3}, [%4];"
                 : "=f"(v.x), "=f"(v.y), "=f"(v.z), "=f"(v.w) : "l"(p));
    return v;
}

__device__ __forceinline__ void stg_stream4(float* p, float4 v) {
    asm volatile("st.global.cs.v4.f32 [%0], {%1,%2,%3,%4};"
                 :: "l"(p), "f"(v.x), "f"(v.y), "f"(v.z), "f"(v.w) : "memory");
}

__global__ __launch_bounds__(256) void idx2pixel_coop4_kernel(
    const float* __restrict__ coords,
    const float* __restrict__ vis,
    float* __restrict__ out,
    int n)
{
    int gtid  = blockIdx.x * blockDim.x + threadIdx.x;
    int w     = gtid >> 5;            // global warp id
    int lane  = threadIdx.x & 31;
    int group = lane >> 2;            // 0..7
    int j     = lane & 3;             // 0..3 within group
    int pbase = (w * 8 + group) * 4;  // first of 4 points
    if (pbase >= n) return;

    unsigned mask = __activemask();
    unsigned long long pol = mk_policy_el();
    const float M = (float)(HW - 4);   // 2044

    // 4 points' coords: two 16B loads (x0,y0,x1,y1) (x2,y2,x3,y3)
    float4 cA = ldg_stream4(coords + (size_t)pbase * 2);
    float4 cB = ldg_stream4(coords + (size_t)pbase * 2 + 4);

    float cx[4] = {cA.x, cA.z, cB.x, cB.z};
    float cy[4] = {cA.y, cA.w, cB.y, cB.w};

    float d0[4], d1[4];
    const float* p0[4];
    const float* p1[4];

    #pragma unroll
    for (int k = 0; k < 4; k++) {
        float c0 = fmodf(cx[k] - 1.0f, M); if (c0 < 0.0f) c0 += M; c0 += 1.0f;
        float c1 = fmodf(cy[k] - 1.0f, M); if (c1 < 0.0f) c1 += M; c1 += 1.0f;
        float f0 = floorf(c0), f1 = floorf(c1);
        d0[k] = c0 - f0;  d1[k] = c1 - f1;
        int i0 = (int)f0, i1 = (int)f1;
        p0[k] = vis + ((size_t)i0 * HW + i1) * CCH + j * 4;
        p1[k] = p0[k] + (size_t)HW * CCH;
    }

    // ---- 8 gather loads in flight ----
    float4 A0 = ldg_vis(p0[0], pol);
    float4 B0 = ldg_vis(p1[0], pol);
    float4 A1 = ldg_vis(p0[1], pol);
    float4 B1 = ldg_vis(p1[1], pol);
    float4 A2 = ldg_vis(p0[2], pol);
    float4 B2 = ldg_vis(p1[2], pol);
    float4 A3 = ldg_vis(p0[3], pol);
    float4 B3 = ldg_vis(p1[3], pol);

    float4 Av[4] = {A0, A1, A2, A3};
    float4 Bv[4] = {B0, B1, B2, B3};

    #pragma unroll
    for (int k = 0; k < 4; k++) {
        // lanes 0,1 -> mt = tr + d0*(tl-tr); lanes 2,3 -> mb = br + d0*(bl-br)
        float4 v;
        v.x = Bv[k].x + d0[k] * (Av[k].x - Bv[k].x);
        v.y = Bv[k].y + d0[k] * (Av[k].y - Bv[k].y);
        v.z = Bv[k].z + d0[k] * (Av[k].z - Bv[k].z);
        v.w = Bv[k].w + d0[k] * (Av[k].w - Bv[k].w);

        float4 o;
        o.x = __shfl_xor_sync(mask, v.x, 2);
        o.y = __shfl_xor_sync(mask, v.y, 2);
        o.z = __shfl_xor_sync(mask, v.z, 2);
        o.w = __shfl_xor_sync(mask, v.w, 2);

        float4 mt, mb;
        if (j < 2) { mt = v; mb = o; } else { mt = o; mb = v; }

        float4 r;
        r.x = mb.x + d1[k] * (mt.x - mb.x);
        r.y = mb.y + d1[k] * (mt.y - mb.y);
        r.z = mb.z + d1[k] * (mt.z - mb.z);
        r.w = mb.w + d1[k] * (mt.w - mb.w);

        // off = c > 2048 never true (c in [1, 2045)): no zeroing.
        if (j < 2 && (pbase + k) < n)
            stg_stream4(out + ((size_t)(pbase + k) * CCH) + j * 4, r);
    }
}

extern "C" void kernel_launch(void* const* d_in, const int* in_sizes, int n_in,
                              void* d_out, int out_size)
{
    const float* coords = (const float*)d_in[0];
    const float* vis    = (const float*)d_in[1];
    float* out          = (float*)d_out;

    int n = in_sizes[0] / 2;             // number of points
    int threads = 256;                    // 8 warps -> 8*8*4 = 256 points/block
    int ppb = (threads / 32) * 8 * 4;
    int blocks = (n + ppb - 1) / ppb;
    idx2pixel_coop4_kernel<<<blocks, threads>>>(coords, vis, out, n);
}